// round 16
// baseline (speedup 1.0000x reference)
#include <cuda_runtime.h>
#include <cuda_fp16.h>

#define NN 100000
#define NE 1600000
#define CH 128
#define BSTRIDE 64                // fixed bucket capacity per node (P(overflow)~1e-13)

typedef unsigned long long ull;

// ---------------- scratch (static device arrays; no allocation) ----------------
__device__ int    g_cnt[NN];                       // real in-degree / bucket cursor
__device__ float  g_dis[NN];                       // (deg+1)^{-1/2}
__device__ int    g_csrc[NN * BSTRIDE];            // fixed-stride adjacency buckets
__device__ __align__(16) __half g_h16[NN * CH];    // layer-1 GEMM out (spmm1 gather)
__device__ __align__(16) __half g_a16[NN * CH];    // layer-1 aggregate, fp16
__device__ __align__(16) __half g_h16b[NN * CH];   // layer-2 GEMM out (spmm2 gather)

// ---------------- packed f32x2 helpers (Blackwell FFMA2 path) ----------------
__device__ __forceinline__ ull pack_dup(float a) {
    ull r;
    asm("mov.b64 %0, {%1, %1};" : "=l"(r) : "f"(a));
    return r;
}
__device__ __forceinline__ void fma2(ull& d, ull a, ull b) {
    asm("fma.rn.f32x2 %0, %1, %2, %0;" : "+l"(d) : "l"(a), "l"(b));
}
__device__ __forceinline__ float2 unpack2(ull v) {
    float2 r;
    asm("mov.b64 {%0, %1}, %2;" : "=f"(r.x), "=f"(r.y) : "l"(v));
    return r;
}

// ---------------- one-pass bucket fill (cnt pre-zeroed by memset) ----------------
__global__ void k_fill(const int* __restrict__ src, const int* __restrict__ dst) {
    int i = blockIdx.x * blockDim.x + threadIdx.x;
    if (i >= NE) return;
    int s = src[i], d = dst[i];
    int pos = atomicAdd(&g_cnt[d], 1);
    if (pos < BSTRIDE) g_csrc[d * BSTRIDE + pos] = s;
}

// ---------------- dis = rsqrt(deg+1) ----------------
__global__ void k_dis() {
    int i = blockIdx.x * blockDim.x + threadIdx.x;
    if (i < NN) g_dis[i] = rsqrtf((float)(g_cnt[i] + 1));
}

// ---------------- SGEMM core (FFMA2, skewed Bs). A loader differs by dtype. --
// fp32-A version (layer 1: A = x)
__global__ __launch_bounds__(256) void k_gemm_f(const float* __restrict__ A,
                                                const float* __restrict__ W,
                                                __half* __restrict__ C, int M) {
    __shared__ float As[8][128];
    __shared__ float Bs[8][160];
    int tid = threadIdx.x;
    int block_row = blockIdx.x * 128;

    int tr = tid >> 4;
    int tc = tid & 15;

    ull acc[8][4];
#pragma unroll
    for (int i = 0; i < 8; i++)
#pragma unroll
        for (int j = 0; j < 4; j++) acc[i][j] = 0ull;

    int arow  = tid >> 1;
    int acol4 = (tid & 1) * 4;
    int brow  = tid >> 5;
    int bcol4 = (tid & 31) * 4;
    int bphys = bcol4 + 2 * (bcol4 >> 3);

#pragma unroll 1
    for (int kk = 0; kk < 128; kk += 8) {
        float4 av = make_float4(0.f, 0.f, 0.f, 0.f);
        int gr = block_row + arow;
        if (gr < M)
            av = *(const float4*)(A + (size_t)gr * 128 + kk + acol4);
        As[acol4 + 0][arow] = av.x;
        As[acol4 + 1][arow] = av.y;
        As[acol4 + 2][arow] = av.z;
        As[acol4 + 3][arow] = av.w;

        float4 bv = *(const float4*)(W + (size_t)(kk + brow) * 128 + bcol4);
        *(float2*)&Bs[brow][bphys]     = make_float2(bv.x, bv.y);
        *(float2*)&Bs[brow][bphys + 2] = make_float2(bv.z, bv.w);
        __syncthreads();

#pragma unroll
        for (int k = 0; k < 8; k++) {
            float4 rm0 = *(const float4*)&As[k][tr * 8];
            float4 rm1 = *(const float4*)&As[k][tr * 8 + 4];
            ull rmd[8];
            rmd[0] = pack_dup(rm0.x); rmd[1] = pack_dup(rm0.y);
            rmd[2] = pack_dup(rm0.z); rmd[3] = pack_dup(rm0.w);
            rmd[4] = pack_dup(rm1.x); rmd[5] = pack_dup(rm1.y);
            rmd[6] = pack_dup(rm1.z); rmd[7] = pack_dup(rm1.w);

            const ull* bp = (const ull*)&Bs[k][tc * 10];
            ull rn0 = bp[0], rn1 = bp[1], rn2 = bp[2], rn3 = bp[3];

#pragma unroll
            for (int i = 0; i < 8; i++) {
                fma2(acc[i][0], rmd[i], rn0);
                fma2(acc[i][1], rmd[i], rn1);
                fma2(acc[i][2], rmd[i], rn2);
                fma2(acc[i][3], rmd[i], rn3);
            }
        }
        __syncthreads();
    }

#pragma unroll
    for (int i = 0; i < 8; i++) {
        int gr = block_row + tr * 8 + i;
        if (gr < M) {
            float2 p0 = unpack2(acc[i][0]);
            float2 p1 = unpack2(acc[i][1]);
            float2 p2 = unpack2(acc[i][2]);
            float2 p3 = unpack2(acc[i][3]);
            __half2 h0 = __float22half2_rn(p0);
            __half2 h1 = __float22half2_rn(p1);
            __half2 h2v = __float22half2_rn(p2);
            __half2 h3 = __float22half2_rn(p3);
            uint4 val;
            val.x = *(unsigned*)&h0; val.y = *(unsigned*)&h1;
            val.z = *(unsigned*)&h2v; val.w = *(unsigned*)&h3;
            uint4* cp = (uint4*)(C + (size_t)gr * 128);
            cp[tc] = val;
        }
    }
}

// fp16-A version (layer 2: A = agg16)
__global__ __launch_bounds__(256) void k_gemm_h(const __half* __restrict__ A,
                                                const float* __restrict__ W,
                                                __half* __restrict__ C, int M) {
    __shared__ float As[8][128];
    __shared__ float Bs[8][160];
    int tid = threadIdx.x;
    int block_row = blockIdx.x * 128;

    int tr = tid >> 4;
    int tc = tid & 15;

    ull acc[8][4];
#pragma unroll
    for (int i = 0; i < 8; i++)
#pragma unroll
        for (int j = 0; j < 4; j++) acc[i][j] = 0ull;

    int arow  = tid >> 1;
    int acol4 = (tid & 1) * 4;
    int brow  = tid >> 5;
    int bcol4 = (tid & 31) * 4;
    int bphys = bcol4 + 2 * (bcol4 >> 3);

#pragma unroll 1
    for (int kk = 0; kk < 128; kk += 8) {
        uint2 hv = make_uint2(0u, 0u);
        int gr = block_row + arow;
        if (gr < M)
            hv = *(const uint2*)(A + (size_t)gr * 128 + kk + acol4);
        float2 f01 = __half22float2(*reinterpret_cast<__half2*>(&hv.x));
        float2 f23 = __half22float2(*reinterpret_cast<__half2*>(&hv.y));
        As[acol4 + 0][arow] = f01.x;
        As[acol4 + 1][arow] = f01.y;
        As[acol4 + 2][arow] = f23.x;
        As[acol4 + 3][arow] = f23.y;

        float4 bv = *(const float4*)(W + (size_t)(kk + brow) * 128 + bcol4);
        *(float2*)&Bs[brow][bphys]     = make_float2(bv.x, bv.y);
        *(float2*)&Bs[brow][bphys + 2] = make_float2(bv.z, bv.w);
        __syncthreads();

#pragma unroll
        for (int k = 0; k < 8; k++) {
            float4 rm0 = *(const float4*)&As[k][tr * 8];
            float4 rm1 = *(const float4*)&As[k][tr * 8 + 4];
            ull rmd[8];
            rmd[0] = pack_dup(rm0.x); rmd[1] = pack_dup(rm0.y);
            rmd[2] = pack_dup(rm0.z); rmd[3] = pack_dup(rm0.w);
            rmd[4] = pack_dup(rm1.x); rmd[5] = pack_dup(rm1.y);
            rmd[6] = pack_dup(rm1.z); rmd[7] = pack_dup(rm1.w);

            const ull* bp = (const ull*)&Bs[k][tc * 10];
            ull rn0 = bp[0], rn1 = bp[1], rn2 = bp[2], rn3 = bp[3];

#pragma unroll
            for (int i = 0; i < 8; i++) {
                fma2(acc[i][0], rmd[i], rn0);
                fma2(acc[i][1], rmd[i], rn1);
                fma2(acc[i][2], rmd[i], rn2);
                fma2(acc[i][3], rmd[i], rn3);
            }
        }
        __syncthreads();
    }

#pragma unroll
    for (int i = 0; i < 8; i++) {
        int gr = block_row + tr * 8 + i;
        if (gr < M) {
            float2 p0 = unpack2(acc[i][0]);
            float2 p1 = unpack2(acc[i][1]);
            float2 p2 = unpack2(acc[i][2]);
            float2 p3 = unpack2(acc[i][3]);
            __half2 h0 = __float22half2_rn(p0);
            __half2 h1 = __float22half2_rn(p1);
            __half2 h2v = __float22half2_rn(p2);
            __half2 h3 = __float22half2_rn(p3);
            uint4 val;
            val.x = *(unsigned*)&h0; val.y = *(unsigned*)&h1;
            val.z = *(unsigned*)&h2v; val.w = *(unsigned*)&h3;
            uint4* cp = (uint4*)(C + (size_t)gr * 128);
            cp[tc] = val;
        }
    }
}

// ---------------- fp16 gather helper ----------------
__device__ __forceinline__ void acc4(float& x, float& y, float& z, float& w,
                                     float s, uint2 u) {
    __half2 p01 = *reinterpret_cast<__half2*>(&u.x);
    __half2 p23 = *reinterpret_cast<__half2*>(&u.y);
    float2 f01 = __half22float2(p01);
    float2 f23 = __half22float2(p23);
    x += s * f01.x; y += s * f01.y; z += s * f23.x; w += s * f23.y;
}

// shared spmm body over fixed-stride buckets
__device__ __forceinline__ void spmm_body(const uint2* __restrict__ h2p,
                                          const float* __restrict__ bias,
                                          int node, int lane,
                                          float& ax, float& ay, float& az, float& aw) {
    float dsi = g_dis[node];
    float sw  = dsi * dsi;

    ax = ay = az = aw = 0.f;
    float bx = 0.f, by = 0.f, bz = 0.f, bw = 0.f;
    acc4(ax, ay, az, aw, sw, h2p[node * 32 + lane]);

    const int* bucket = g_csrc + node * BSTRIDE;
    int cnt = g_cnt[node];
    if (cnt > BSTRIDE) cnt = BSTRIDE;

    int e = 0;
    for (; e + 3 < cnt; e += 4) {
        int s0 = bucket[e];
        int s1 = bucket[e + 1];
        int s2 = bucket[e + 2];
        int s3 = bucket[e + 3];
        float w0 = g_dis[s0] * dsi;
        float w1 = g_dis[s1] * dsi;
        float w2 = g_dis[s2] * dsi;
        float w3 = g_dis[s3] * dsi;
        uint2 v0 = h2p[s0 * 32 + lane];
        uint2 v1 = h2p[s1 * 32 + lane];
        uint2 v2 = h2p[s2 * 32 + lane];
        uint2 v3 = h2p[s3 * 32 + lane];
        acc4(ax, ay, az, aw, w0, v0);
        acc4(bx, by, bz, bw, w1, v1);
        acc4(ax, ay, az, aw, w2, v2);
        acc4(bx, by, bz, bw, w3, v3);
    }
    for (; e < cnt; e++) {
        int s0 = bucket[e];
        float w0 = g_dis[s0] * dsi;
        acc4(ax, ay, az, aw, w0, h2p[s0 * 32 + lane]);
    }

    float4 bb = ((const float4*)bias)[lane];
    ax += bx + bb.x; ay += by + bb.y; az += bz + bb.z; aw += bw + bb.w;
}

// layer 1: agg + b1 + relu -> fp16 rows
__global__ __launch_bounds__(256) void k_spmm_h(const __half* __restrict__ h,
                                                const float* __restrict__ bias,
                                                __half* __restrict__ out) {
    int node = (blockIdx.x * blockDim.x + threadIdx.x) >> 5;
    if (node >= NN) return;
    int lane = threadIdx.x & 31;
    float ax, ay, az, aw;
    spmm_body((const uint2*)h, bias, node, lane, ax, ay, az, aw);
    ax = fmaxf(ax, 0.f); ay = fmaxf(ay, 0.f);
    az = fmaxf(az, 0.f); aw = fmaxf(aw, 0.f);
    __half2 h0 = __floats2half2_rn(ax, ay);
    __half2 h1 = __floats2half2_rn(az, aw);
    uint2 o;
    o.x = *(unsigned*)&h0;
    o.y = *(unsigned*)&h1;
    ((uint2*)out)[node * 32 + lane] = o;
}

// layer 2: agg + b2 -> fp32 output
__global__ __launch_bounds__(256) void k_spmm_f(const __half* __restrict__ h,
                                                const float* __restrict__ bias,
                                                float* __restrict__ out) {
    int node = (blockIdx.x * blockDim.x + threadIdx.x) >> 5;
    if (node >= NN) return;
    int lane = threadIdx.x & 31;
    float ax, ay, az, aw;
    spmm_body((const uint2*)h, bias, node, lane, ax, ay, az, aw);
    ((float4*)out)[node * 32 + lane] = make_float4(ax, ay, az, aw);
}

// ---------------- launch (fork-join: bucket build || layer-1 GEMM) -------------
extern "C" void kernel_launch(void* const* d_in, const int* in_sizes, int n_in,
                              void* d_out, int out_size) {
    // metadata order: x, last_update, edge_index, t, msg, W1, b1, W2, b2
    const float* x  = (const float*)d_in[0];
    const int*   ei = (const int*)d_in[2];
    const float* W1 = (const float*)d_in[5];
    const float* b1 = (const float*)d_in[6];
    const float* W2 = (const float*)d_in[7];
    const float* b2 = (const float*)d_in[8];
    float* out = (float*)d_out;

    const int* src = ei;        // edge_index[0]
    const int* dst = ei + NE;   // edge_index[1]

    __half *h16, *a16, *h16b;
    int* cntAddr;
    cudaGetSymbolAddress((void**)&h16,  g_h16);
    cudaGetSymbolAddress((void**)&a16,  g_a16);
    cudaGetSymbolAddress((void**)&h16b, g_h16b);
    cudaGetSymbolAddress((void**)&cntAddr, g_cnt);

    cudaStream_t side;
    cudaStreamCreateWithFlags(&side, cudaStreamNonBlocking);
    cudaEvent_t evFork, evJoin;
    cudaEventCreateWithFlags(&evFork, cudaEventDisableTiming);
    cudaEventCreateWithFlags(&evJoin, cudaEventDisableTiming);

    cudaEventRecord(evFork, 0);
    cudaStreamWaitEvent(side, evFork, 0);

    // bucket build on side stream: memset -> one-pass fill -> dis
    cudaMemsetAsync(cntAddr, 0, NN * sizeof(int), side);
    k_fill<<<(NE + 255) / 256, 256, 0, side>>>(src, dst);
    k_dis <<<(NN + 255) / 256, 256, 0, side>>>();
    cudaEventRecord(evJoin, side);

    // Layer-1 GEMM concurrently on main stream
    k_gemm_f<<<(NN + 127) / 128, 256>>>(x, W1, h16, NN);

    cudaStreamWaitEvent(0, evJoin, 0);   // spmm1 needs gemm1 + buckets

    // layer 1 aggregation (fp16 out), layer 2 GEMM (fp16 in), layer 2 aggregation
    k_spmm_h<<<(NN * 32 + 255) / 256, 256>>>(h16, b1, a16);
    k_gemm_h<<<(NN + 127) / 128, 256>>>(a16, W2, h16b, NN);
    k_spmm_f<<<(NN * 32 + 255) / 256, 256>>>(h16b, b2, out);

    cudaEventDestroy(evFork);
    cudaEventDestroy(evJoin);
    cudaStreamDestroy(side);
}

// round 17
// speedup vs baseline: 1.0857x; 1.0857x over previous
#include <cuda_runtime.h>
#include <cuda_fp16.h>

#define NN 100000
#define NE 1600000
#define CH 128
#define SCAN_CHUNK 512
#define SCAN_NB ((NN + SCAN_CHUNK - 1) / SCAN_CHUNK)   // 196 (< 256)

typedef unsigned long long ull;

// ---------------- scratch (static device arrays; no allocation) ----------------
__device__ int    g_deg[NN];          // real in-degree; zero at entry, re-zeroed by scanC
__device__ int    g_cur[NN];          // fill cursors (seeded to g_off in scanC)
__device__ int    g_off[NN + 1];      // CSR row offsets (real edges only)
__device__ float  g_dis[NN];          // (deg+1)^{-1/2}
__device__ int    g_bsum[SCAN_NB];
__device__ int    g_csrc[NE];         // CSR src per slot
__device__ __align__(16) __half g_h16[NN * CH];    // layer-1 GEMM out (spmm1 gather)
__device__ __align__(16) __half g_a16[NN * CH];    // layer-1 aggregate, fp16
__device__ __align__(16) __half g_h16b[NN * CH];   // layer-2 GEMM out (spmm2 gather)

// ---------------- packed f32x2 helpers (Blackwell FFMA2 path) ----------------
__device__ __forceinline__ ull pack_dup(float a) {
    ull r;
    asm("mov.b64 %0, {%1, %1};" : "=l"(r) : "f"(a));
    return r;
}
__device__ __forceinline__ void fma2(ull& d, ull a, ull b) {
    asm("fma.rn.f32x2 %0, %1, %2, %0;" : "+l"(d) : "l"(a), "l"(b));
}
__device__ __forceinline__ float2 unpack2(ull v) {
    float2 r;
    asm("mov.b64 {%0, %1}, %2;" : "=f"(r.x), "=f"(r.y) : "l"(v));
    return r;
}

// ---------------- degree count (deg zero at entry) ----------------
__global__ void k_count(const int* __restrict__ dst) {
    int i = blockIdx.x * blockDim.x + threadIdx.x;
    if (i < NE) atomicAdd(&g_deg[dst[i]], 1);
}

// ---------------- scan phase A: per-block sums + dis ----------------
__global__ __launch_bounds__(256) void k_scanA() {
    __shared__ int sh[256];
    int tid = threadIdx.x;
    int base = blockIdx.x * SCAN_CHUNK;
    int s = 0;
#pragma unroll
    for (int j = 0; j < 2; j++) {
        int i = base + tid * 2 + j;
        if (i < NN) {
            int d = g_deg[i];                 // real in-degree
            g_dis[i] = rsqrtf((float)(d + 1));
            s += d;
        }
    }
    sh[tid] = s;
    __syncthreads();
#pragma unroll
    for (int off = 128; off > 0; off >>= 1) {
        if (tid < off) sh[tid] += sh[tid + off];
        __syncthreads();
    }
    if (tid == 0) g_bsum[blockIdx.x] = sh[0];
}

// ---------------- scan phase C (absorbs old phase B): offsets + cursor seed
// + deg reset for the next run. Each block reduces its own bsum prefix.
__global__ __launch_bounds__(256) void k_scanC() {
    __shared__ int sh[256];
    int tid = threadIdx.x;

    // block base = sum of g_bsum[0 .. blockIdx.x)   (SCAN_NB <= 256)
    int v = (tid < blockIdx.x) ? g_bsum[tid] : 0;
    sh[tid] = v;
    __syncthreads();
#pragma unroll
    for (int off = 128; off > 0; off >>= 1) {
        if (tid < off) sh[tid] += sh[tid + off];
        __syncthreads();
    }
    int base_excl = sh[0];
    __syncthreads();

    // local pair scan
    int base = blockIdx.x * SCAN_CHUNK;
    int i0 = base + tid * 2;
    int d0 = (i0 < NN)     ? g_deg[i0]     : 0;
    int d1 = (i0 + 1 < NN) ? g_deg[i0 + 1] : 0;
    if (i0 < NN)     g_deg[i0]     = 0;     // reset for next run
    if (i0 + 1 < NN) g_deg[i0 + 1] = 0;
    int pair = d0 + d1;
    sh[tid] = pair;
    __syncthreads();
#pragma unroll
    for (int off = 1; off < 256; off <<= 1) {
        int t = (tid >= off) ? sh[tid - off] : 0;
        __syncthreads();
        sh[tid] += t;
        __syncthreads();
    }
    int excl = base_excl + sh[tid] - pair;
    if (i0 < NN)     { g_off[i0]     = excl;      g_cur[i0]     = excl; }
    if (i0 + 1 < NN) { g_off[i0 + 1] = excl + d0; g_cur[i0 + 1] = excl + d0; }
    if (blockIdx.x == SCAN_NB - 1 && tid == 255)
        g_off[NN] = base_excl + sh[255];    // grand total
}

// ---------------- CSR fill ----------------
__global__ void k_fill(const int* __restrict__ src, const int* __restrict__ dst) {
    int i = blockIdx.x * blockDim.x + threadIdx.x;
    if (i >= NE) return;
    int s = src[i], d = dst[i];
    int pos = atomicAdd(&g_cur[d], 1);
    g_csrc[pos] = s;
}

// ---------------- SGEMM core (FFMA2, skewed Bs). A loader differs by dtype. --
// fp32-A version (layer 1: A = x)
__global__ __launch_bounds__(256) void k_gemm_f(const float* __restrict__ A,
                                                const float* __restrict__ W,
                                                __half* __restrict__ C, int M) {
    __shared__ float As[8][128];
    __shared__ float Bs[8][160];
    int tid = threadIdx.x;
    int block_row = blockIdx.x * 128;

    int tr = tid >> 4;
    int tc = tid & 15;

    ull acc[8][4];
#pragma unroll
    for (int i = 0; i < 8; i++)
#pragma unroll
        for (int j = 0; j < 4; j++) acc[i][j] = 0ull;

    int arow  = tid >> 1;
    int acol4 = (tid & 1) * 4;
    int brow  = tid >> 5;
    int bcol4 = (tid & 31) * 4;
    int bphys = bcol4 + 2 * (bcol4 >> 3);

#pragma unroll 1
    for (int kk = 0; kk < 128; kk += 8) {
        float4 av = make_float4(0.f, 0.f, 0.f, 0.f);
        int gr = block_row + arow;
        if (gr < M)
            av = *(const float4*)(A + (size_t)gr * 128 + kk + acol4);
        As[acol4 + 0][arow] = av.x;
        As[acol4 + 1][arow] = av.y;
        As[acol4 + 2][arow] = av.z;
        As[acol4 + 3][arow] = av.w;

        float4 bv = *(const float4*)(W + (size_t)(kk + brow) * 128 + bcol4);
        *(float2*)&Bs[brow][bphys]     = make_float2(bv.x, bv.y);
        *(float2*)&Bs[brow][bphys + 2] = make_float2(bv.z, bv.w);
        __syncthreads();

#pragma unroll
        for (int k = 0; k < 8; k++) {
            float4 rm0 = *(const float4*)&As[k][tr * 8];
            float4 rm1 = *(const float4*)&As[k][tr * 8 + 4];
            ull rmd[8];
            rmd[0] = pack_dup(rm0.x); rmd[1] = pack_dup(rm0.y);
            rmd[2] = pack_dup(rm0.z); rmd[3] = pack_dup(rm0.w);
            rmd[4] = pack_dup(rm1.x); rmd[5] = pack_dup(rm1.y);
            rmd[6] = pack_dup(rm1.z); rmd[7] = pack_dup(rm1.w);

            const ull* bp = (const ull*)&Bs[k][tc * 10];
            ull rn0 = bp[0], rn1 = bp[1], rn2 = bp[2], rn3 = bp[3];

#pragma unroll
            for (int i = 0; i < 8; i++) {
                fma2(acc[i][0], rmd[i], rn0);
                fma2(acc[i][1], rmd[i], rn1);
                fma2(acc[i][2], rmd[i], rn2);
                fma2(acc[i][3], rmd[i], rn3);
            }
        }
        __syncthreads();
    }

#pragma unroll
    for (int i = 0; i < 8; i++) {
        int gr = block_row + tr * 8 + i;
        if (gr < M) {
            float2 p0 = unpack2(acc[i][0]);
            float2 p1 = unpack2(acc[i][1]);
            float2 p2 = unpack2(acc[i][2]);
            float2 p3 = unpack2(acc[i][3]);
            __half2 h0 = __float22half2_rn(p0);
            __half2 h1 = __float22half2_rn(p1);
            __half2 h2v = __float22half2_rn(p2);
            __half2 h3 = __float22half2_rn(p3);
            uint4 val;
            val.x = *(unsigned*)&h0; val.y = *(unsigned*)&h1;
            val.z = *(unsigned*)&h2v; val.w = *(unsigned*)&h3;
            uint4* cp = (uint4*)(C + (size_t)gr * 128);
            cp[tc] = val;
        }
    }
}

// fp16-A version (layer 2: A = agg16)
__global__ __launch_bounds__(256) void k_gemm_h(const __half* __restrict__ A,
                                                const float* __restrict__ W,
                                                __half* __restrict__ C, int M) {
    __shared__ float As[8][128];
    __shared__ float Bs[8][160];
    int tid = threadIdx.x;
    int block_row = blockIdx.x * 128;

    int tr = tid >> 4;
    int tc = tid & 15;

    ull acc[8][4];
#pragma unroll
    for (int i = 0; i < 8; i++)
#pragma unroll
        for (int j = 0; j < 4; j++) acc[i][j] = 0ull;

    int arow  = tid >> 1;
    int acol4 = (tid & 1) * 4;
    int brow  = tid >> 5;
    int bcol4 = (tid & 31) * 4;
    int bphys = bcol4 + 2 * (bcol4 >> 3);

#pragma unroll 1
    for (int kk = 0; kk < 128; kk += 8) {
        uint2 hv = make_uint2(0u, 0u);
        int gr = block_row + arow;
        if (gr < M)
            hv = *(const uint2*)(A + (size_t)gr * 128 + kk + acol4);
        float2 f01 = __half22float2(*reinterpret_cast<__half2*>(&hv.x));
        float2 f23 = __half22float2(*reinterpret_cast<__half2*>(&hv.y));
        As[acol4 + 0][arow] = f01.x;
        As[acol4 + 1][arow] = f01.y;
        As[acol4 + 2][arow] = f23.x;
        As[acol4 + 3][arow] = f23.y;

        float4 bv = *(const float4*)(W + (size_t)(kk + brow) * 128 + bcol4);
        *(float2*)&Bs[brow][bphys]     = make_float2(bv.x, bv.y);
        *(float2*)&Bs[brow][bphys + 2] = make_float2(bv.z, bv.w);
        __syncthreads();

#pragma unroll
        for (int k = 0; k < 8; k++) {
            float4 rm0 = *(const float4*)&As[k][tr * 8];
            float4 rm1 = *(const float4*)&As[k][tr * 8 + 4];
            ull rmd[8];
            rmd[0] = pack_dup(rm0.x); rmd[1] = pack_dup(rm0.y);
            rmd[2] = pack_dup(rm0.z); rmd[3] = pack_dup(rm0.w);
            rmd[4] = pack_dup(rm1.x); rmd[5] = pack_dup(rm1.y);
            rmd[6] = pack_dup(rm1.z); rmd[7] = pack_dup(rm1.w);

            const ull* bp = (const ull*)&Bs[k][tc * 10];
            ull rn0 = bp[0], rn1 = bp[1], rn2 = bp[2], rn3 = bp[3];

#pragma unroll
            for (int i = 0; i < 8; i++) {
                fma2(acc[i][0], rmd[i], rn0);
                fma2(acc[i][1], rmd[i], rn1);
                fma2(acc[i][2], rmd[i], rn2);
                fma2(acc[i][3], rmd[i], rn3);
            }
        }
        __syncthreads();
    }

#pragma unroll
    for (int i = 0; i < 8; i++) {
        int gr = block_row + tr * 8 + i;
        if (gr < M) {
            float2 p0 = unpack2(acc[i][0]);
            float2 p1 = unpack2(acc[i][1]);
            float2 p2 = unpack2(acc[i][2]);
            float2 p3 = unpack2(acc[i][3]);
            __half2 h0 = __float22half2_rn(p0);
            __half2 h1 = __float22half2_rn(p1);
            __half2 h2v = __float22half2_rn(p2);
            __half2 h3 = __float22half2_rn(p3);
            uint4 val;
            val.x = *(unsigned*)&h0; val.y = *(unsigned*)&h1;
            val.z = *(unsigned*)&h2v; val.w = *(unsigned*)&h3;
            uint4* cp = (uint4*)(C + (size_t)gr * 128);
            cp[tc] = val;
        }
    }
}

// ---------------- fp16 gather helper ----------------
__device__ __forceinline__ void acc4(float& x, float& y, float& z, float& w,
                                     float s, uint2 u) {
    __half2 p01 = *reinterpret_cast<__half2*>(&u.x);
    __half2 p23 = *reinterpret_cast<__half2*>(&u.y);
    float2 f01 = __half22float2(p01);
    float2 f23 = __half22float2(p23);
    x += s * f01.x; y += s * f01.y; z += s * f23.x; w += s * f23.y;
}

// shared spmm body: 8-deep gather unroll (MLP=8), then 4, then scalar tail
__device__ __forceinline__ void spmm_body(const uint2* __restrict__ h2p,
                                          const float* __restrict__ bias,
                                          int node, int lane,
                                          float& ax, float& ay, float& az, float& aw) {
    float dsi = g_dis[node];
    float sw  = dsi * dsi;

    ax = ay = az = aw = 0.f;
    float bx = 0.f, by = 0.f, bz = 0.f, bw = 0.f;
    acc4(ax, ay, az, aw, sw, h2p[node * 32 + lane]);

    int e   = g_off[node];
    int end = g_off[node + 1];

    // 8-deep: 8 independent gathers in flight per warp
    for (; e + 7 < end; e += 8) {
        int s[8]; float w[8]; uint2 v[8];
#pragma unroll
        for (int j = 0; j < 8; j++) s[j] = g_csrc[e + j];
#pragma unroll
        for (int j = 0; j < 8; j++) v[j] = h2p[s[j] * 32 + lane];
#pragma unroll
        for (int j = 0; j < 8; j++) w[j] = g_dis[s[j]] * dsi;
#pragma unroll
        for (int j = 0; j < 8; j += 2) {
            acc4(ax, ay, az, aw, w[j],     v[j]);
            acc4(bx, by, bz, bw, w[j + 1], v[j + 1]);
        }
    }
    // 4-deep mid loop
    for (; e + 3 < end; e += 4) {
        int s[4]; float w[4]; uint2 v[4];
#pragma unroll
        for (int j = 0; j < 4; j++) s[j] = g_csrc[e + j];
#pragma unroll
        for (int j = 0; j < 4; j++) v[j] = h2p[s[j] * 32 + lane];
#pragma unroll
        for (int j = 0; j < 4; j++) w[j] = g_dis[s[j]] * dsi;
        acc4(ax, ay, az, aw, w[0], v[0]);
        acc4(bx, by, bz, bw, w[1], v[1]);
        acc4(ax, ay, az, aw, w[2], v[2]);
        acc4(bx, by, bz, bw, w[3], v[3]);
    }
    for (; e < end; e++) {
        int s0 = g_csrc[e];
        float w0 = g_dis[s0] * dsi;
        acc4(ax, ay, az, aw, w0, h2p[s0 * 32 + lane]);
    }

    float4 bb = ((const float4*)bias)[lane];
    ax += bx + bb.x; ay += by + bb.y; az += bz + bb.z; aw += bw + bb.w;
}

// layer 1: agg + b1 + relu -> fp16 rows
__global__ __launch_bounds__(256) void k_spmm_h(const __half* __restrict__ h,
                                                const float* __restrict__ bias,
                                                __half* __restrict__ out) {
    int node = (blockIdx.x * blockDim.x + threadIdx.x) >> 5;
    if (node >= NN) return;
    int lane = threadIdx.x & 31;
    float ax, ay, az, aw;
    spmm_body((const uint2*)h, bias, node, lane, ax, ay, az, aw);
    ax = fmaxf(ax, 0.f); ay = fmaxf(ay, 0.f);
    az = fmaxf(az, 0.f); aw = fmaxf(aw, 0.f);
    __half2 h0 = __floats2half2_rn(ax, ay);
    __half2 h1 = __floats2half2_rn(az, aw);
    uint2 o;
    o.x = *(unsigned*)&h0;
    o.y = *(unsigned*)&h1;
    ((uint2*)out)[node * 32 + lane] = o;
}

// layer 2: agg + b2 -> fp32 output
__global__ __launch_bounds__(256) void k_spmm_f(const __half* __restrict__ h,
                                                const float* __restrict__ bias,
                                                float* __restrict__ out) {
    int node = (blockIdx.x * blockDim.x + threadIdx.x) >> 5;
    if (node >= NN) return;
    int lane = threadIdx.x & 31;
    float ax, ay, az, aw;
    spmm_body((const uint2*)h, bias, node, lane, ax, ay, az, aw);
    ((float4*)out)[node * 32 + lane] = make_float4(ax, ay, az, aw);
}

// ---------------- launch (fork-join: CSR build || layer-1 GEMM) ----------------
extern "C" void kernel_launch(void* const* d_in, const int* in_sizes, int n_in,
                              void* d_out, int out_size) {
    // metadata order: x, last_update, edge_index, t, msg, W1, b1, W2, b2
    const float* x  = (const float*)d_in[0];
    const int*   ei = (const int*)d_in[2];
    const float* W1 = (const float*)d_in[5];
    const float* b1 = (const float*)d_in[6];
    const float* W2 = (const float*)d_in[7];
    const float* b2 = (const float*)d_in[8];
    float* out = (float*)d_out;

    const int* src = ei;        // edge_index[0]
    const int* dst = ei + NE;   // edge_index[1]

    __half *h16, *a16, *h16b;
    cudaGetSymbolAddress((void**)&h16,  g_h16);
    cudaGetSymbolAddress((void**)&a16,  g_a16);
    cudaGetSymbolAddress((void**)&h16b, g_h16b);

    cudaStream_t side;
    cudaStreamCreateWithFlags(&side, cudaStreamNonBlocking);
    cudaEvent_t evFork, evJoin;
    cudaEventCreateWithFlags(&evFork, cudaEventDisableTiming);
    cudaEventCreateWithFlags(&evJoin, cudaEventDisableTiming);

    cudaEventRecord(evFork, 0);
    cudaStreamWaitEvent(side, evFork, 0);

    // CSR build chain on side stream (deg zero at entry; scanC re-zeroes it)
    k_count<<<(NE + 255) / 256, 256, 0, side>>>(dst);
    k_scanA<<<SCAN_NB, 256, 0, side>>>();
    k_scanC<<<SCAN_NB, 256, 0, side>>>();
    k_fill <<<(NE + 255) / 256, 256, 0, side>>>(src, dst);
    cudaEventRecord(evJoin, side);

    // Layer-1 GEMM concurrently on main stream
    k_gemm_f<<<(NN + 127) / 128, 256>>>(x, W1, h16, NN);

    cudaStreamWaitEvent(0, evJoin, 0);   // spmm1 needs gemm1 + CSR

    // layer 1 aggregation (fp16 out), layer 2 GEMM (fp16 in), layer 2 aggregation
    k_spmm_h<<<(NN * 32 + 255) / 256, 256>>>(h16, b1, a16);
    k_gemm_h<<<(NN + 127) / 128, 256>>>(a16, W2, h16b, NN);
    k_spmm_f<<<(NN * 32 + 255) / 256, 256>>>(h16b, b2, out);

    cudaEventDestroy(evFork);
    cudaEventDestroy(evJoin);
    cudaStreamDestroy(side);
}